// round 1
// baseline (speedup 1.0000x reference)
#include <cuda_runtime.h>

// Problem geometry: x[32][512][512][2] float32, NHWC. FILTER_SIZE=61.
#define NB   32
#define HH   512
#define WW   512
#define RAD  30          // (61-1)/2
#define FSF  61

static constexpr float SCALE = 1.0f / (61.0f * 61.0f * 2.0f);  // 1/(fs*fs*C)
static constexpr float EPS   = 1e-7f;

static constexpr int NPIX = NB * HH * WW;       // float2 elements (C packed)
static constexpr int COLS = NB * WW;            // 16384 float2 columns
static constexpr int SEG  = 64;                 // rows per thread in vertical pass
static constexpr int VTHREADS = COLS * (HH / SEG);  // 131072

// Scratch (allocation-free rule: __device__ globals)
__device__ float2 g_t1[NPIX];   // V-box(x)
__device__ float2 g_d [NPIX];   // d = x - avg(x)
__device__ float2 g_t2[NPIX];   // V-box(d)
__device__ float2 g_t3[NPIX];   // V-box(d^2)

// ---------------------------------------------------------------------------
// K1: vertical 61-tap box sum of x -> g_t1. One thread per (n,w) column
// segment of SEG rows; channels packed in float2.
// ---------------------------------------------------------------------------
__global__ void k1_vbox_x(const float2* __restrict__ x) {
    int idx = blockIdx.x * blockDim.x + threadIdx.x;
    int col = idx & (COLS - 1);
    int seg = idx >> 14;                 // COLS = 2^14
    int n = col >> 9;                    // WW = 512
    int w = col & (WW - 1);
    const float2* p = x    + (size_t)n * HH * WW + w;
    float2*       q = g_t1 + (size_t)n * HH * WW + w;

    int h0 = seg * SEG;
    float sx = 0.f, sy = 0.f;
    int jlo = h0 - RAD; if (jlo < 0) jlo = 0;
    int jhi = h0 + RAD; if (jhi > HH - 1) jhi = HH - 1;
    for (int j = jlo; j <= jhi; ++j) {
        float2 v = p[(size_t)j * WW];
        sx += v.x; sy += v.y;
    }
    #pragma unroll 4
    for (int h = h0; h < h0 + SEG; ++h) {
        q[(size_t)h * WW] = make_float2(sx, sy);
        int ha = h + RAD + 1;
        if (ha < HH) { float2 v = p[(size_t)ha * WW]; sx += v.x; sy += v.y; }
        int hr = h - RAD;
        if (hr >= 0) { float2 v = p[(size_t)hr * WW]; sx -= v.x; sy -= v.y; }
    }
}

// ---------------------------------------------------------------------------
// K3: vertical box of d and d^2 in one pass -> g_t2, g_t3
// ---------------------------------------------------------------------------
__global__ void k3_vbox_d(void) {
    int idx = blockIdx.x * blockDim.x + threadIdx.x;
    int col = idx & (COLS - 1);
    int seg = idx >> 14;
    int n = col >> 9;
    int w = col & (WW - 1);
    size_t base = (size_t)n * HH * WW + w;
    const float2* p = g_d + base;
    float2* q2 = g_t2 + base;
    float2* q3 = g_t3 + base;

    int h0 = seg * SEG;
    float sx = 0.f, sy = 0.f, qx = 0.f, qy = 0.f;
    int jlo = h0 - RAD; if (jlo < 0) jlo = 0;
    int jhi = h0 + RAD; if (jhi > HH - 1) jhi = HH - 1;
    for (int j = jlo; j <= jhi; ++j) {
        float2 v = p[(size_t)j * WW];
        sx += v.x; sy += v.y;
        qx += v.x * v.x; qy += v.y * v.y;
    }
    #pragma unroll 4
    for (int h = h0; h < h0 + SEG; ++h) {
        q2[(size_t)h * WW] = make_float2(sx, sy);
        q3[(size_t)h * WW] = make_float2(qx, qy);
        int ha = h + RAD + 1;
        if (ha < HH) {
            float2 v = p[(size_t)ha * WW];
            sx += v.x; sy += v.y; qx += v.x * v.x; qy += v.y * v.y;
        }
        int hr = h - RAD;
        if (hr >= 0) {
            float2 v = p[(size_t)hr * WW];
            sx -= v.x; sy -= v.y; qx -= v.x * v.x; qy -= v.y * v.y;
        }
    }
}

// ---------------------------------------------------------------------------
// Block-wide inclusive scans (512 threads). float2 and float4 variants.
// ---------------------------------------------------------------------------
__device__ __forceinline__ float2 block_scan2(float2 v, float2* sP) {
    __shared__ float2 wsum2[16];
    int tid = threadIdx.x, lane = tid & 31, wp = tid >> 5;
    #pragma unroll
    for (int o = 1; o < 32; o <<= 1) {
        float ax = __shfl_up_sync(0xffffffffu, v.x, o);
        float ay = __shfl_up_sync(0xffffffffu, v.y, o);
        if (lane >= o) { v.x += ax; v.y += ay; }
    }
    if (lane == 31) wsum2[wp] = v;
    __syncthreads();
    if (tid < 16) {
        float2 s = wsum2[tid];
        #pragma unroll
        for (int o = 1; o < 16; o <<= 1) {
            float ax = __shfl_up_sync(0x0000ffffu, s.x, o);
            float ay = __shfl_up_sync(0x0000ffffu, s.y, o);
            if (tid >= o) { s.x += ax; s.y += ay; }
        }
        wsum2[tid] = s;
    }
    __syncthreads();
    if (wp > 0) { float2 o = wsum2[wp - 1]; v.x += o.x; v.y += o.y; }
    sP[tid] = v;
    __syncthreads();
    return v;
}

__device__ __forceinline__ float4 block_scan4(float4 v, float4* sP) {
    __shared__ float4 wsum4[16];
    int tid = threadIdx.x, lane = tid & 31, wp = tid >> 5;
    #pragma unroll
    for (int o = 1; o < 32; o <<= 1) {
        float ax = __shfl_up_sync(0xffffffffu, v.x, o);
        float ay = __shfl_up_sync(0xffffffffu, v.y, o);
        float az = __shfl_up_sync(0xffffffffu, v.z, o);
        float aw = __shfl_up_sync(0xffffffffu, v.w, o);
        if (lane >= o) { v.x += ax; v.y += ay; v.z += az; v.w += aw; }
    }
    if (lane == 31) wsum4[wp] = v;
    __syncthreads();
    if (tid < 16) {
        float4 s = wsum4[tid];
        #pragma unroll
        for (int o = 1; o < 16; o <<= 1) {
            float ax = __shfl_up_sync(0x0000ffffu, s.x, o);
            float ay = __shfl_up_sync(0x0000ffffu, s.y, o);
            float az = __shfl_up_sync(0x0000ffffu, s.z, o);
            float aw = __shfl_up_sync(0x0000ffffu, s.w, o);
            if (tid >= o) { s.x += ax; s.y += ay; s.z += az; s.w += aw; }
        }
        wsum4[tid] = s;
    }
    __syncthreads();
    if (wp > 0) {
        float4 o = wsum4[wp - 1];
        v.x += o.x; v.y += o.y; v.z += o.z; v.w += o.w;
    }
    sP[tid] = v;
    __syncthreads();
    return v;
}

// ---------------------------------------------------------------------------
// K2: horizontal box of g_t1 via prefix scan; d = x - SCALE*boxsum -> g_d
// One block per (n,h) row, 512 threads (one float2 pixel each).
// ---------------------------------------------------------------------------
__global__ void k2_hbox_avg(const float2* __restrict__ x) {
    __shared__ float2 sP[WW];
    int w = threadIdx.x;
    size_t row = (size_t)blockIdx.x * WW;

    float2 v = g_t1[row + w];
    block_scan2(v, sP);

    int hi_i = w + RAD; if (hi_i > WW - 1) hi_i = WW - 1;
    float2 hi = sP[hi_i];
    float2 lo = make_float2(0.f, 0.f);
    if (w >= RAD + 1) lo = sP[w - RAD - 1];

    float2 xi = x[row + w];
    float2 dv;
    dv.x = xi.x - (hi.x - lo.x) * SCALE;
    dv.y = xi.y - (hi.y - lo.y) * SCALE;
    g_d[row + w] = dv;
}

// ---------------------------------------------------------------------------
// K4: horizontal box of g_t2/g_t3 via one float4 scan; final normalize.
// ---------------------------------------------------------------------------
__global__ void k4_hbox_out(float2* __restrict__ out) {
    __shared__ float4 sP[WW];
    int w = threadIdx.x;
    size_t row = (size_t)blockIdx.x * WW;

    float2 a = g_t2[row + w];
    float2 b = g_t3[row + w];
    float4 v = make_float4(a.x, a.y, b.x, b.y);
    block_scan4(v, sP);

    int hi_i = w + RAD; if (hi_i > WW - 1) hi_i = WW - 1;
    float4 hi = sP[hi_i];
    float4 lo = make_float4(0.f, 0.f, 0.f, 0.f);
    if (w >= RAD + 1) lo = sP[w - RAD - 1];

    float c1x = (hi.x - lo.x) * SCALE;
    float c1y = (hi.y - lo.y) * SCALE;
    float c2x = (hi.z - lo.z) * SCALE;
    float c2y = (hi.w - lo.w) * SCALE;

    float vx = fmaxf(c2x - c1x * c1x, 0.f);
    float vy = fmaxf(c2y - c1y * c1y, 0.f);

    float2 dv = g_d[row + w];
    float2 o;
    o.x = dv.x / (sqrtf(vx) + EPS);
    o.y = dv.y / (sqrtf(vy) + EPS);
    out[row + w] = o;
}

// ---------------------------------------------------------------------------
extern "C" void kernel_launch(void* const* d_in, const int* in_sizes, int n_in,
                              void* d_out, int out_size) {
    const float2* x = (const float2*)d_in[0];
    float2* out = (float2*)d_out;

    k1_vbox_x<<<VTHREADS / 256, 256>>>(x);
    k2_hbox_avg<<<NB * HH, WW>>>(x);
    k3_vbox_d<<<VTHREADS / 256, 256>>>();
    k4_hbox_out<<<NB * HH, WW>>>(out);
}

// round 4
// speedup vs baseline: 1.3344x; 1.3344x over previous
#include <cuda_runtime.h>
#include <cuda_fp16.h>

// x[32][512][512][2] float32 NHWC, FILTER_SIZE=61, SAME (clipped) box windows.
#define NB   32
#define HH   512
#define WW   512
#define RAD  30

static constexpr float SCALE = 1.0f / (61.0f * 61.0f * 2.0f);  // 1/(fs*fs*C)
static constexpr float EPS   = 1e-7f;

static constexpr int NPIX = NB * HH * WW;   // float2 pixels (C packed)
static constexpr int COLS = NB * WW;        // 16384 columns
static constexpr int SEG  = 32;             // rows per thread, vertical passes
static constexpr int VTH  = COLS * (HH / SEG);  // 262144 threads

// Scratch (__device__ globals: allocation-free rule).
// __align__(16): these are accessed through float4/uint4 casts — 128-bit
// LDG/STG traps (err715) if the array base lands on an 8-mod-16 address.
__device__ __align__(16) __half2 g_t1[NPIX];  // vbox(x), fp16
__device__ __align__(16) float2  g_d [NPIX];  // d = x - avg(x), fp32
__device__ __align__(16) uint2   g_hh[NPIX];  // {half2 hbox(d), half2 hbox(d^2)}

// ---------------------------------------------------------------------------
// P1: vertical 61-tap box sum of x -> g_t1 (half2). Thread per (col, seg).
// ---------------------------------------------------------------------------
__global__ void p1_vbox(const float2* __restrict__ x) {
    int idx = blockIdx.x * blockDim.x + threadIdx.x;
    int col = idx & (COLS - 1);
    int seg = idx >> 14;                 // COLS = 2^14
    int n = col >> 9;
    int w = col & (WW - 1);
    const float2* p = x    + (size_t)n * HH * WW + w;
    __half2*      q = g_t1 + (size_t)n * HH * WW + w;

    int h0 = seg * SEG;
    float sx = 0.f, sy = 0.f;
    int jlo = max(h0 - RAD, 0);
    int jhi = min(h0 + RAD, HH - 1);
    for (int j = jlo; j <= jhi; ++j) {
        float2 v = p[(size_t)j * WW];
        sx += v.x; sy += v.y;
    }
    #pragma unroll 8
    for (int h = h0; h < h0 + SEG; ++h) {
        q[(size_t)h * WW] = __floats2half2_rn(sx, sy);
        int ha = h + RAD + 1;
        if (ha < HH) { float2 v = p[(size_t)ha * WW]; sx += v.x; sy += v.y; }
        int hr = h - RAD;
        if (hr >= 0) { float2 v = p[(size_t)hr * WW]; sx -= v.x; sy -= v.y; }
    }
}

// ---------------------------------------------------------------------------
// Block scans for 256 threads (8 warps).
// ---------------------------------------------------------------------------
__device__ __forceinline__ float2 bscan2(float2 v) {
    __shared__ float2 ws[8];
    int tid = threadIdx.x, lane = tid & 31, wp = tid >> 5;
    #pragma unroll
    for (int o = 1; o < 32; o <<= 1) {
        float ax = __shfl_up_sync(0xffffffffu, v.x, o);
        float ay = __shfl_up_sync(0xffffffffu, v.y, o);
        if (lane >= o) { v.x += ax; v.y += ay; }
    }
    if (lane == 31) ws[wp] = v;
    __syncthreads();
    if (tid < 8) {
        float2 s = ws[tid];
        #pragma unroll
        for (int o = 1; o < 8; o <<= 1) {
            float ax = __shfl_up_sync(0x000000ffu, s.x, o);
            float ay = __shfl_up_sync(0x000000ffu, s.y, o);
            if (tid >= o) { s.x += ax; s.y += ay; }
        }
        ws[tid] = s;
    }
    __syncthreads();
    if (wp > 0) { float2 o = ws[wp - 1]; v.x += o.x; v.y += o.y; }
    return v;
}

__device__ __forceinline__ float4 bscan4(float4 v) {
    __shared__ float4 ws4[8];
    int tid = threadIdx.x, lane = tid & 31, wp = tid >> 5;
    #pragma unroll
    for (int o = 1; o < 32; o <<= 1) {
        float ax = __shfl_up_sync(0xffffffffu, v.x, o);
        float ay = __shfl_up_sync(0xffffffffu, v.y, o);
        float az = __shfl_up_sync(0xffffffffu, v.z, o);
        float aw = __shfl_up_sync(0xffffffffu, v.w, o);
        if (lane >= o) { v.x += ax; v.y += ay; v.z += az; v.w += aw; }
    }
    if (lane == 31) ws4[wp] = v;
    __syncthreads();
    if (tid < 8) {
        float4 s = ws4[tid];
        #pragma unroll
        for (int o = 1; o < 8; o <<= 1) {
            float ax = __shfl_up_sync(0x000000ffu, s.x, o);
            float ay = __shfl_up_sync(0x000000ffu, s.y, o);
            float az = __shfl_up_sync(0x000000ffu, s.z, o);
            float aw = __shfl_up_sync(0x000000ffu, s.w, o);
            if (tid >= o) { s.x += ax; s.y += ay; s.z += az; s.w += aw; }
        }
        ws4[tid] = s;
    }
    __syncthreads();
    if (wp > 0) {
        float4 o = ws4[wp - 1];
        v.x += o.x; v.y += o.y; v.z += o.z; v.w += o.w;
    }
    return v;
}

// ---------------------------------------------------------------------------
// P2: per row (block = one (n,h) row, 256 threads, 2 pixels/thread):
//   1) scan g_t1 row -> windowed hbox -> m = avg(x); d = x - m  (store fp32)
//   2) scan (d, d^2) -> windowed hbox -> g_hh (packed fp16)
// ---------------------------------------------------------------------------
__global__ void p2_hbox(const float4* __restrict__ x4) {
    __shared__ float2 sP[WW];
    __shared__ float4 sQ[WW];
    int t = threadIdx.x;                       // 0..255
    size_t rowp = (size_t)blockIdx.x * WW;     // pixel base of this row

    // --- first scan: prefix of vbox(x) ---
    size_t i0 = rowp + 2 * t;
    float2 e0 = __half22float2(g_t1[i0]);
    float2 e1 = __half22float2(g_t1[i0 + 1]);
    float2 s  = make_float2(e0.x + e1.x, e0.y + e1.y);
    float2 incl = bscan2(s);
    float2 p0 = make_float2(incl.x - e1.x, incl.y - e1.y);  // prefix through e0
    sP[2 * t]     = p0;
    sP[2 * t + 1] = incl;
    __syncthreads();

    float4 xv = x4[(size_t)blockIdx.x * 256 + t];
    float2 dpix[2];
    #pragma unroll
    for (int k = 0; k < 2; ++k) {
        int w = 2 * t + k;
        float2 hi = sP[min(w + RAD, WW - 1)];
        float2 lo = (w >= RAD + 1) ? sP[w - RAD - 1] : make_float2(0.f, 0.f);
        float mx = (hi.x - lo.x) * SCALE;
        float my = (hi.y - lo.y) * SCALE;
        float xx = k ? xv.z : xv.x;
        float xy = k ? xv.w : xv.y;
        dpix[k] = make_float2(xx - mx, xy - my);
    }
    // store d (one float4 = both pixels)
    reinterpret_cast<float4*>(g_d)[(size_t)blockIdx.x * 256 + t] =
        make_float4(dpix[0].x, dpix[0].y, dpix[1].x, dpix[1].y);

    // --- second scan: prefix of (d, d^2) ---
    float4 q0 = make_float4(dpix[0].x, dpix[0].y,
                            dpix[0].x * dpix[0].x, dpix[0].y * dpix[0].y);
    float4 q1 = make_float4(dpix[1].x, dpix[1].y,
                            dpix[1].x * dpix[1].x, dpix[1].y * dpix[1].y);
    float4 s4 = make_float4(q0.x + q1.x, q0.y + q1.y, q0.z + q1.z, q0.w + q1.w);
    float4 incl4 = bscan4(s4);
    float4 pq0 = make_float4(incl4.x - q1.x, incl4.y - q1.y,
                             incl4.z - q1.z, incl4.w - q1.w);
    sQ[2 * t]     = pq0;
    sQ[2 * t + 1] = incl4;
    __syncthreads();

    uint4 outpack;
    #pragma unroll
    for (int k = 0; k < 2; ++k) {
        int w = 2 * t + k;
        float4 hi = sQ[min(w + RAD, WW - 1)];
        float4 lo = (w >= RAD + 1) ? sQ[w - RAD - 1]
                                   : make_float4(0.f, 0.f, 0.f, 0.f);
        __half2 ha = __floats2half2_rn(hi.x - lo.x, hi.y - lo.y);   // hbox(d)
        __half2 hb = __floats2half2_rn(hi.z - lo.z, hi.w - lo.w);   // hbox(d^2)
        unsigned int ua = *reinterpret_cast<unsigned int*>(&ha);
        unsigned int ub = *reinterpret_cast<unsigned int*>(&hb);
        if (k == 0) { outpack.x = ua; outpack.y = ub; }
        else        { outpack.z = ua; outpack.w = ub; }
    }
    reinterpret_cast<uint4*>(g_hh)[(size_t)blockIdx.x * 256 + t] = outpack;
}

// ---------------------------------------------------------------------------
// P3: vertical box of hbox(d), hbox(d^2); final out = d / (sqrt(var)+eps).
// ---------------------------------------------------------------------------
__device__ __forceinline__ void unpack_hh(uint2 u, float2& a, float2& b) {
    __half2 ha = *reinterpret_cast<__half2*>(&u.x);
    __half2 hb = *reinterpret_cast<__half2*>(&u.y);
    a = __half22float2(ha);
    b = __half22float2(hb);
}

__global__ void p3_vbox_out(float2* __restrict__ out) {
    int idx = blockIdx.x * blockDim.x + threadIdx.x;
    int col = idx & (COLS - 1);
    int seg = idx >> 14;
    int n = col >> 9;
    int w = col & (WW - 1);
    size_t base = (size_t)n * HH * WW + w;
    const uint2*  ph = g_hh + base;
    const float2* pd = g_d  + base;
    float2*       po = out  + base;

    int h0 = seg * SEG;
    float s1x = 0.f, s1y = 0.f, s2x = 0.f, s2y = 0.f;
    int jlo = max(h0 - RAD, 0);
    int jhi = min(h0 + RAD, HH - 1);
    for (int j = jlo; j <= jhi; ++j) {
        float2 a, b;
        unpack_hh(ph[(size_t)j * WW], a, b);
        s1x += a.x; s1y += a.y; s2x += b.x; s2y += b.y;
    }
    #pragma unroll 4
    for (int h = h0; h < h0 + SEG; ++h) {
        float c1x = s1x * SCALE, c1y = s1y * SCALE;
        float c2x = s2x * SCALE, c2y = s2y * SCALE;
        float vx = fmaxf(c2x - c1x * c1x, 0.f);
        float vy = fmaxf(c2y - c1y * c1y, 0.f);
        float sdx = sqrtf(vx) + EPS;
        float sdy = sqrtf(vy) + EPS;
        float2 dv = pd[(size_t)h * WW];
        po[(size_t)h * WW] = make_float2(__fdividef(dv.x, sdx),
                                         __fdividef(dv.y, sdy));
        int ha = h + RAD + 1;
        if (ha < HH) {
            float2 a, b;
            unpack_hh(ph[(size_t)ha * WW], a, b);
            s1x += a.x; s1y += a.y; s2x += b.x; s2y += b.y;
        }
        int hr = h - RAD;
        if (hr >= 0) {
            float2 a, b;
            unpack_hh(ph[(size_t)hr * WW], a, b);
            s1x -= a.x; s1y -= a.y; s2x -= b.x; s2y -= b.y;
        }
    }
}

// ---------------------------------------------------------------------------
extern "C" void kernel_launch(void* const* d_in, const int* in_sizes, int n_in,
                              void* d_out, int out_size) {
    const float2* x = (const float2*)d_in[0];
    float2* out = (float2*)d_out;

    p1_vbox<<<VTH / 256, 256>>>(x);
    p2_hbox<<<NB * HH, 256>>>((const float4*)x);
    p3_vbox_out<<<VTH / 256, 256>>>(out);
}